// round 15
// baseline (speedup 1.0000x reference)
#include <cuda_runtime.h>
#include <cuda_fp16.h>
#include <cuda_bf16.h>
#include <cstdint>

// GAT N=2048, IN=1024, H=8, F=32, slope=0.2 — fused HMMA pipeline (3 kernels).
//  K1 adjbits:     adj int32 -> bitmask words, strided ballot (MLP=8)
//  K2 hgemm_fused: g = h @ W (fp16 HMMA); epilogue computes per-(node,h) fp16
//                  u1,u2,e1,e2,thr AND writes g as mma B-fragments (40 N-rows:
//                  f0..31=g, f32=ones->Z col, f33..39=0). No g materialization.
//  K3 attn:        half2 W-gen in A-fragment registers (no exp), mma.sync,
//                  128-row i-tiles, NSPLIT=4 j-splits; LAST split-CTA per
//                  (i-tile,hg) reduces partials + normalizes (threadfence
//                  reduction) -> out. No separate norm kernel.

#define N_NODES 2048
#define IN_F    1024
#define NH      8
#define NF      32
#define GDIM    256
#define NSPLIT  4
#define JSPAN   (N_NODES/NSPLIT)   // 512

__device__ __half g_u1h[NH * N_NODES];
__device__ __half g_u2h[NH * N_NODES];
__device__ __half g_e1h[NH * N_NODES];
__device__ __half g_e2h[NH * N_NODES];
__device__ __half g_thrh[NH * N_NODES];
__device__ uint2  g_bfragHI[NH * 128 * 5 * 32];
__device__ uint32_t g_adjbits[N_NODES * (N_NODES / 32)];
__device__ float  g_pnum[NSPLIT][N_NODES * GDIM];
__device__ float  g_pz[NSPLIT][N_NODES * NH];
__device__ unsigned g_cnt[(N_NODES / 128) * 2];   // zero-init; reset by reducer

__device__ __forceinline__ uint32_t h2u(__half2 v) { return *(uint32_t*)&v; }
__device__ __forceinline__ __half2 u2h2(uint32_t v) { return *(__half2*)&v; }

__device__ __forceinline__ void mma16816(float* c, const uint32_t* a, const uint2 b) {
    asm volatile(
        "mma.sync.aligned.m16n8k16.row.col.f32.f16.f16.f32 "
        "{%0,%1,%2,%3}, {%4,%5,%6,%7}, {%8,%9}, {%0,%1,%2,%3};"
        : "+f"(c[0]), "+f"(c[1]), "+f"(c[2]), "+f"(c[3])
        : "r"(a[0]), "r"(a[1]), "r"(a[2]), "r"(a[3]), "r"(b.x), "r"(b.y));
}

// ---------------- K1: adjacency -> bitmask words ----------------
__global__ __launch_bounds__(256) void adjbits_kernel(const int* __restrict__ adj) {
    const int w = blockIdx.x * 8 + (threadIdx.x >> 5);
    const int lane = threadIdx.x & 31;
    const long base = (long)w * 256;
    int v[8];
#pragma unroll
    for (int s = 0; s < 8; s++) v[s] = adj[base + s * 32 + lane];
    uint32_t m[8];
#pragma unroll
    for (int s = 0; s < 8; s++) m[s] = __ballot_sync(0xFFFFFFFFu, v[s] != 0);
    uint32_t out = m[0];
#pragma unroll
    for (int s = 1; s < 8; s++) out = (lane == s) ? m[s] : out;
    if (lane < 8) g_adjbits[w * 8 + lane] = out;
}

// ---------------- K2: fused g = h@W (fp16 HMMA) + score + bfrag ----------------
#define TSTRIDE 68
__global__ __launch_bounds__(256) void hgemm_fused(const float* __restrict__ A,
                                                   const float* __restrict__ B,
                                                   const float* __restrict__ av) {
    __shared__ __half2 Ah[2][2*4*32*4];   // 8 KB
    __shared__ __half2 Bh[2][2*8*32*2];   // 8 KB
    __shared__ float   tile[64][TSTRIDE]; // 17.4 KB
    __shared__ float   as[2 * NF];

    const int tid = threadIdx.x, wid = tid >> 5, lane = tid & 31;
    const int bm = blockIdx.y << 6, bn = blockIdx.x << 6;
    const int wm = wid & 1, wn = wid >> 1;

    if (tid < 2 * NF) as[tid] = av[tid];

    const int arow = tid >> 2, akh = (tid & 3) * 8;
    const int bkp = tid & 15, bn4 = (tid >> 4) * 4;
    const int bksub = bkp >> 3, breg = (bkp >> 2) & 1, blq = bkp & 3;

    float fa[8], fb[8];
    auto ldgA = [&](int k0) {
        const float* p = &A[(bm + arow) * IN_F + k0 + akh];
        float4 v0 = *(const float4*)p;
        float4 v1 = *(const float4*)(p + 4);
        fa[0]=v0.x; fa[1]=v0.y; fa[2]=v0.z; fa[3]=v0.w;
        fa[4]=v1.x; fa[5]=v1.y; fa[6]=v1.z; fa[7]=v1.w;
    };
    auto ldgB = [&](int k0) {
        const float* p0 = &B[(k0 + 2*bkp) * GDIM + bn + bn4];
        float4 v0 = *(const float4*)p0;
        float4 v1 = *(const float4*)(p0 + GDIM);
        fb[0]=v0.x; fb[1]=v0.y; fb[2]=v0.z; fb[3]=v0.w;
        fb[4]=v1.x; fb[5]=v1.y; fb[6]=v1.z; fb[7]=v1.w;
    };
    auto sts = [&](int buf) {
#pragma unroll
        for (int p = 0; p < 4; p++) {
            int kkl = akh + 2 * p;
            __half hh0 = __float2half_rn(fa[2*p]), hh1 = __float2half_rn(fa[2*p + 1]);
            int ksub = kkl >> 4, kk16 = kkl & 15;
            int reg = ((arow >> 3) & 1) + ((kk16 >= 8) ? 2 : 0);
            int ln  = (arow & 7) * 4 + ((kk16 & 7) >> 1);
            Ah[buf][((ksub * 4 + (arow >> 4)) * 32 + ln) * 4 + reg] = __halves2half2(hh0, hh1);
        }
#pragma unroll
        for (int n = 0; n < 4; n++) {
            int ng = bn4 + n;
            __half hh0 = __float2half_rn(fb[n]), hh1 = __float2half_rn(fb[4 + n]);
            int ln  = (ng & 7) * 4 + blq;
            Bh[buf][((bksub * 8 + (ng >> 3)) * 32 + ln) * 2 + breg] = __halves2half2(hh0, hh1);
        }
    };

    float acc[2][2][4];
#pragma unroll
    for (int mf = 0; mf < 2; mf++)
#pragma unroll
        for (int nf = 0; nf < 2; nf++)
#pragma unroll
            for (int q = 0; q < 4; q++) acc[mf][nf][q] = 0.f;

    ldgA(0); ldgB(0);
    sts(0);

    for (int c = 0; c < IN_F / 32; c++) {
        __syncthreads();
        const int buf = c & 1;
        if (c + 1 < IN_F / 32) { ldgA((c + 1) * 32); ldgB((c + 1) * 32); }
#pragma unroll
        for (int ks = 0; ks < 2; ks++) {
            uint4 ahi[2];
            uint2 bhi[2];
#pragma unroll
            for (int mf = 0; mf < 2; mf++)
                ahi[mf] = *(uint4*)&Ah[buf][((ks * 4 + wm * 2 + mf) * 32 + lane) * 4];
#pragma unroll
            for (int nf = 0; nf < 2; nf++)
                bhi[nf] = *(uint2*)&Bh[buf][((ks * 8 + wn * 2 + nf) * 32 + lane) * 2];
#pragma unroll
            for (int mf = 0; mf < 2; mf++) {
                uint32_t ah[4] = {ahi[mf].x, ahi[mf].y, ahi[mf].z, ahi[mf].w};
#pragma unroll
                for (int nf = 0; nf < 2; nf++) mma16816(acc[mf][nf], ah, bhi[nf]);
            }
        }
        if (c + 1 < IN_F / 32) sts((c + 1) & 1);
    }

    // ---- epilogue: stage tile, then score + bfrag ----
    const int rq = lane >> 2, cq = (lane & 3) * 2;
    __syncthreads();
#pragma unroll
    for (int mf = 0; mf < 2; mf++) {
        int r0 = (wm * 2 + mf) * 16 + rq;
#pragma unroll
        for (int nf = 0; nf < 2; nf++) {
            int col = (wn * 2 + nf) * 8 + cq;
            tile[r0][col]     = acc[mf][nf][0];
            tile[r0][col + 1] = acc[mf][nf][1];
            tile[r0 + 8][col]     = acc[mf][nf][2];
            tile[r0 + 8][col + 1] = acc[mf][nf][3];
        }
    }
    __syncthreads();

    if (tid < 128) {   // score: 64 rows x 2 heads
        int row = tid & 63, hh = tid >> 6;
        int node = bm + row;
        int head = (bn >> 5) + hh;
        const float* tp = &tile[row][hh * 32];
        float sl = 0.f, sr = 0.f;
#pragma unroll
        for (int c = 0; c < 8; c++) {
            float4 v = *(const float4*)&tp[c * 4];
            sl = fmaf(v.x, as[c*4+0], sl); sl = fmaf(v.y, as[c*4+1], sl);
            sl = fmaf(v.z, as[c*4+2], sl); sl = fmaf(v.w, as[c*4+3], sl);
            sr = fmaf(v.x, as[NF+c*4+0], sr); sr = fmaf(v.y, as[NF+c*4+1], sr);
            sr = fmaf(v.z, as[NF+c*4+2], sr); sr = fmaf(v.w, as[NF+c*4+3], sr);
        }
        const int o = head * N_NODES + node;
        g_u1h[o]  = __float2half_rn(expf(sr));
        g_u2h[o]  = __float2half_rn(expf(0.2f * sr));
        g_e1h[o]  = __float2half_rn(expf(sl));
        g_e2h[o]  = __float2half_rn(expf(0.2f * sl));
        g_thrh[o] = __float2half_rn(expf(-sl));
    }

    // bfrag: 40 fragments per CTA, 8 warps x 5
    const int n = lane >> 2, kq = (lane & 3) * 2;
#pragma unroll
    for (int t = 0; t < 5; t++) {
        int fid = wid * 5 + t;
        uint2 frag;
        int hh, jgl, nfr;
        if (fid < 32) {
            hh = fid >> 4; jgl = (fid >> 2) & 3; nfr = fid & 3;
            int f = nfr * 8 + n;
            float v[4];
#pragma unroll
            for (int r = 0; r < 2; r++)
#pragma unroll
                for (int s = 0; s < 2; s++)
                    v[r * 2 + s] = tile[jgl * 16 + r * 8 + kq + s][hh * 32 + f];
            frag = make_uint2(
                h2u(__halves2half2(__float2half_rn(v[0]), __float2half_rn(v[1]))),
                h2u(__halves2half2(__float2half_rn(v[2]), __float2half_rn(v[3]))));
        } else {
            int p = fid - 32;
            hh = p >> 2; jgl = p & 3; nfr = 4;
            uint32_t ones = (n == 0) ? 0x3C003C00u : 0u;
            frag = make_uint2(ones, ones);
        }
        int head = (bn >> 5) + hh;
        int jg = (bm >> 4) + jgl;
        g_bfragHI[((long)(head * 128 + jg) * 5 + nfr) * 32 + lane] = frag;
    }
}

// ---------------- K3: HMMA attention + fused final reduction/normalize ----------------
__global__ __launch_bounds__(256, 1) void attn_kernel(float* __restrict__ out) {
    __shared__ uint32_t adjw[2][128];
    __shared__ __half u1s[2][128];   // [4 h][32 j]
    __shared__ __half u2s[2][128];
    __shared__ unsigned s_done;

    const int tid = threadIdx.x, wid = tid >> 5, lane = tid & 31;
    const int i0 = blockIdx.x * 128;
    const int hg = blockIdx.y;
    const int sp = blockIdx.z;
    const int j00 = sp * JSPAN;

    const int hloc  = wid >> 1;
    const int hglob = hg * 4 + hloc;
    const int ihalf = (wid & 1) * 64;
    const int rq = lane >> 2;
    const int kq = (lane & 3) * 2;

    __half2 th2[4][2], e2b[4][2], ed[4][2];
#pragma unroll
    for (int mf = 0; mf < 4; mf++)
#pragma unroll
        for (int rs = 0; rs < 2; rs++) {
            int r = i0 + ihalf + mf * 16 + rq + rs * 8;
            __half e1 = g_e1h[hglob * N_NODES + r];
            __half e2 = g_e2h[hglob * N_NODES + r];
            th2[mf][rs] = __half2half2(g_thrh[hglob * N_NODES + r]);
            e2b[mf][rs] = __half2half2(e2);
            ed[mf][rs]  = __half2half2(__hsub(e1, e2));
        }

    float acc[4][5][4];
#pragma unroll
    for (int mf = 0; mf < 4; mf++)
#pragma unroll
        for (int nf = 0; nf < 5; nf++)
#pragma unroll
            for (int q = 0; q < 4; q++) acc[mf][nf][q] = 0.f;

    {   // stage chunk 0
        const int j0c = j00;
        if (tid < 128) {
            adjw[0][tid] = g_adjbits[(i0 + tid) * (N_NODES / 32) + (j0c >> 5)];
            u1s[0][tid] = g_u1h[(hg * 4 + (tid >> 5)) * N_NODES + j0c + (tid & 31)];
        } else {
            int q = tid - 128;
            u2s[0][q] = g_u2h[(hg * 4 + (q >> 5)) * N_NODES + j0c + (q & 31)];
        }
    }
    __syncthreads();

    for (int c = 0; c < 16; c++) {
        const int j0c = j00 + c * 32;
        const int buf = c & 1;
        uint2 bh[2][5];
#pragma unroll
        for (int ks = 0; ks < 2; ks++) {
            const long bbase = ((long)(hglob * 128 + (j0c >> 4) + ks) * 5) * 32 + lane;
#pragma unroll
            for (int nf = 0; nf < 5; nf++) bh[ks][nf] = g_bfragHI[bbase + nf * 32];
        }
        if (c + 1 < 16) {
            const int j0n = j0c + 32;
            if (tid < 128) {
                adjw[buf ^ 1][tid] = g_adjbits[(i0 + tid) * (N_NODES / 32) + (j0n >> 5)];
                u1s[buf ^ 1][tid] = g_u1h[(hg * 4 + (tid >> 5)) * N_NODES + j0n + (tid & 31)];
            } else {
                int q = tid - 128;
                u2s[buf ^ 1][q] = g_u2h[(hg * 4 + (q >> 5)) * N_NODES + j0n + (q & 31)];
            }
        }

#pragma unroll
        for (int kstep = 0; kstep < 2; kstep++) {
            const int jb = kstep * 16 + kq;
            __half2 u1a = *(const __half2*)&u1s[buf][hloc * 32 + jb];
            __half2 u1b = *(const __half2*)&u1s[buf][hloc * 32 + jb + 8];
            __half2 u2a = *(const __half2*)&u2s[buf][hloc * 32 + jb];
            __half2 u2b = *(const __half2*)&u2s[buf][hloc * 32 + jb + 8];
            __half2 uda = __hsub2(u1a, u2a);
            __half2 udb = __hsub2(u1b, u2b);

#pragma unroll
            for (int mf = 0; mf < 4; mf++) {
                uint32_t aw0 = adjw[buf][ihalf + mf * 16 + rq];
                uint32_t aw1 = adjw[buf][ihalf + mf * 16 + rq + 8];
                uint32_t areg[4];
#pragma unroll
                for (int rs = 0; rs < 2; rs++) {
                    uint32_t aw = rs ? aw1 : aw0;
                    __half2 th = th2[mf][rs], e2r = e2b[mf][rs], edr = ed[mf][rs];
                    uint32_t ba = (aw >> jb) & 3u;
                    uint32_t ma = ((ba & 1u) * 0x3C00u) | ((ba >> 1) * 0x3C000000u);
                    __half2 m  = __hge2(u1a, th);
                    __half2 t  = __hfma2(m, uda, u2a);
                    __half2 e  = __hfma2(m, edr, e2r);
                    __half2 w  = __hmul2(__hmul2(t, e), u2h2(ma));
                    areg[rs] = h2u(w);
                    uint32_t bb = (aw >> (jb + 8)) & 3u;
                    uint32_t mb = ((bb & 1u) * 0x3C00u) | ((bb >> 1) * 0x3C000000u);
                    __half2 m2 = __hge2(u1b, th);
                    __half2 t2 = __hfma2(m2, udb, u2b);
                    __half2 e2x = __hfma2(m2, edr, e2r);
                    __half2 w2 = __hmul2(__hmul2(t2, e2x), u2h2(mb));
                    areg[rs + 2] = h2u(w2);
                }
#pragma unroll
                for (int nf = 0; nf < 5; nf++) mma16816(acc[mf][nf], areg, bh[kstep][nf]);
            }
        }
        __syncthreads();
    }

#pragma unroll
    for (int mf = 0; mf < 4; mf++) {
        int r0 = i0 + ihalf + mf * 16 + rq;
        int r1 = r0 + 8;
#pragma unroll
        for (int nf = 0; nf < 4; nf++) {
            int f = nf * 8 + kq;
            *(float2*)&g_pnum[sp][r0 * GDIM + hglob * NF + f] =
                make_float2(acc[mf][nf][0], acc[mf][nf][1]);
            *(float2*)&g_pnum[sp][r1 * GDIM + hglob * NF + f] =
                make_float2(acc[mf][nf][2], acc[mf][nf][3]);
        }
        if ((lane & 3) == 0) {
            g_pz[sp][r0 * NH + hglob] = acc[mf][4][0];
            g_pz[sp][r1 * NH + hglob] = acc[mf][4][2];
        }
    }

    // ---- threadfence reduction: last split-CTA normalizes this (i-tile, hg) ----
    __threadfence();
    __syncthreads();
    if (tid == 0) s_done = atomicAdd(&g_cnt[blockIdx.x * 2 + hg], 1);
    __syncthreads();
    if (s_done == NSPLIT - 1) {
        const int row = i0 + (tid >> 1);
        const int ch = (tid & 1) * 64;          // 0 or 64 within the 128-col band
        const int colbase = hg * 128 + ch;
        const int head0 = hg * 4 + (ch >> 5);   // covers head0, head0+1
        float z0 = 0.f, z1 = 0.f;
#pragma unroll
        for (int s = 0; s < NSPLIT; s++) {
            z0 += g_pz[s][row * NH + head0];
            z1 += g_pz[s][row * NH + head0 + 1];
        }
        const float inv0 = 1.0f / z0, inv1 = 1.0f / z1;
#pragma unroll
        for (int q = 0; q < 16; q++) {
            const int col = colbase + q * 4;
            float4 v0 = *(const float4*)&g_pnum[0][row * GDIM + col];
            float4 v1 = *(const float4*)&g_pnum[1][row * GDIM + col];
            float4 v2 = *(const float4*)&g_pnum[2][row * GDIM + col];
            float4 v3 = *(const float4*)&g_pnum[3][row * GDIM + col];
            const float inv = (q < 8) ? inv0 : inv1;
            float4 r;
            r.x = ((v0.x + v1.x) + (v2.x + v3.x)) * inv;
            r.y = ((v0.y + v1.y) + (v2.y + v3.y)) * inv;
            r.z = ((v0.z + v1.z) + (v2.z + v3.z)) * inv;
            r.w = ((v0.w + v1.w) + (v2.w + v3.w)) * inv;
            *(float4*)&out[row * GDIM + col] = r;
        }
        if (tid == 0) g_cnt[blockIdx.x * 2 + hg] = 0;   // reset for next replay
    }
}

extern "C" void kernel_launch(void* const* d_in, const int* in_sizes, int n_in,
                              void* d_out, int out_size) {
    const float* h_ptr = nullptr;
    const int*   adj   = nullptr;
    const float* W_ptr = nullptr;
    const float* a_ptr = nullptr;
    for (int i = 0; i < n_in; i++) {
        long sz = in_sizes[i];
        if (sz == (long)N_NODES * IN_F)          h_ptr = (const float*)d_in[i];
        else if (sz == (long)N_NODES * N_NODES)  adj   = (const int*)d_in[i];
        else if (sz == (long)IN_F * GDIM)        W_ptr = (const float*)d_in[i];
        else if (sz == 2 * NF)                   a_ptr = (const float*)d_in[i];
    }
    float* out = (float*)d_out;

    adjbits_kernel<<<(N_NODES * (N_NODES / 32)) / 64, 256>>>(adj);
    hgemm_fused<<<dim3(GDIM / 64, N_NODES / 64), 256>>>(h_ptr, W_ptr, a_ptr);
    attn_kernel<<<dim3(N_NODES / 128, 2, NSPLIT), 256>>>(out);
}

// round 16
// speedup vs baseline: 1.2622x; 1.2622x over previous
#include <cuda_runtime.h>
#include <cuda_fp16.h>
#include <cuda_bf16.h>
#include <cstdint>

// GAT N=2048, IN=1024, H=8, F=32, slope=0.2 — fused HMMA pipeline (3 kernels).
//  K1 hgemm_fused: g = h @ W (fp16 HMMA) + interleaved adj->bitmask conversion
//                  (4 words/warp/k-iter, hidden under MMA latency); epilogue
//                  computes per-(node,h) fp16 u1,u2,e1,e2,thr AND writes g as
//                  mma B-fragments (40 N-rows: f0..31=g, f32=ones->Z, pad 0).
//  K2 attn:        half2 W-gen in A-fragment registers (no exp), mma.sync,
//                  128-row i-tiles, NSPLIT=4 j-splits
//  K3 norm:        out = sum(num)/sum(Z), 4 floats/thread, 512 CTAs

#define N_NODES 2048
#define IN_F    1024
#define NH      8
#define NF      32
#define GDIM    256
#define NSPLIT  4
#define JSPAN   (N_NODES/NSPLIT)   // 512

__device__ __half g_u1h[NH * N_NODES];
__device__ __half g_u2h[NH * N_NODES];
__device__ __half g_e1h[NH * N_NODES];
__device__ __half g_e2h[NH * N_NODES];
__device__ __half g_thrh[NH * N_NODES];
__device__ uint2  g_bfragHI[NH * 128 * 5 * 32];
__device__ uint32_t g_adjbits[N_NODES * (N_NODES / 32)];
__device__ float  g_pnum[NSPLIT][N_NODES * GDIM];
__device__ float  g_pz[NSPLIT][N_NODES * NH];

__device__ __forceinline__ uint32_t h2u(__half2 v) { return *(uint32_t*)&v; }
__device__ __forceinline__ __half2 u2h2(uint32_t v) { return *(__half2*)&v; }

__device__ __forceinline__ void mma16816(float* c, const uint32_t* a, const uint2 b) {
    asm volatile(
        "mma.sync.aligned.m16n8k16.row.col.f32.f16.f16.f32 "
        "{%0,%1,%2,%3}, {%4,%5,%6,%7}, {%8,%9}, {%0,%1,%2,%3};"
        : "+f"(c[0]), "+f"(c[1]), "+f"(c[2]), "+f"(c[3])
        : "r"(a[0]), "r"(a[1]), "r"(a[2]), "r"(a[3]), "r"(b.x), "r"(b.y));
}

// ---------------- K1: fused g = h@W (fp16 HMMA) + adjbits + score + bfrag ----------------
#define TSTRIDE 68
__global__ __launch_bounds__(256) void hgemm_fused(const float* __restrict__ A,
                                                   const float* __restrict__ B,
                                                   const float* __restrict__ av,
                                                   const int* __restrict__ adj) {
    __shared__ __half2 Ah[2][2*4*32*4];   // 8 KB
    __shared__ __half2 Bh[2][2*8*32*2];   // 8 KB
    __shared__ float   tile[64][TSTRIDE]; // 17.4 KB
    __shared__ float   as[2 * NF];

    const int tid = threadIdx.x, wid = tid >> 5, lane = tid & 31;
    const int bm = blockIdx.y << 6, bn = blockIdx.x << 6;
    const int wm = wid & 1, wn = wid >> 1;

    if (tid < 2 * NF) as[tid] = av[tid];

    // adjbits slice: CTA handles 1024 words, warp 128, 4 per k-iter
    const int cta = blockIdx.y * 4 + blockIdx.x;     // gridDim.x == 4
    const long wbase = (long)cta * 1024 + wid * 128;

    const int arow = tid >> 2, akh = (tid & 3) * 8;
    const int bkp = tid & 15, bn4 = (tid >> 4) * 4;
    const int bksub = bkp >> 3, breg = (bkp >> 2) & 1, blq = bkp & 3;

    float fa[8], fb[8];
    auto ldgA = [&](int k0) {
        const float* p = &A[(bm + arow) * IN_F + k0 + akh];
        float4 v0 = *(const float4*)p;
        float4 v1 = *(const float4*)(p + 4);
        fa[0]=v0.x; fa[1]=v0.y; fa[2]=v0.z; fa[3]=v0.w;
        fa[4]=v1.x; fa[5]=v1.y; fa[6]=v1.z; fa[7]=v1.w;
    };
    auto ldgB = [&](int k0) {
        const float* p0 = &B[(k0 + 2*bkp) * GDIM + bn + bn4];
        float4 v0 = *(const float4*)p0;
        float4 v1 = *(const float4*)(p0 + GDIM);
        fb[0]=v0.x; fb[1]=v0.y; fb[2]=v0.z; fb[3]=v0.w;
        fb[4]=v1.x; fb[5]=v1.y; fb[6]=v1.z; fb[7]=v1.w;
    };
    auto sts = [&](int buf) {
#pragma unroll
        for (int p = 0; p < 4; p++) {
            int kkl = akh + 2 * p;
            __half hh0 = __float2half_rn(fa[2*p]), hh1 = __float2half_rn(fa[2*p + 1]);
            int ksub = kkl >> 4, kk16 = kkl & 15;
            int reg = ((arow >> 3) & 1) + ((kk16 >= 8) ? 2 : 0);
            int ln  = (arow & 7) * 4 + ((kk16 & 7) >> 1);
            Ah[buf][((ksub * 4 + (arow >> 4)) * 32 + ln) * 4 + reg] = __halves2half2(hh0, hh1);
        }
#pragma unroll
        for (int n = 0; n < 4; n++) {
            int ng = bn4 + n;
            __half hh0 = __float2half_rn(fb[n]), hh1 = __float2half_rn(fb[4 + n]);
            int ln  = (ng & 7) * 4 + blq;
            Bh[buf][((bksub * 8 + (ng >> 3)) * 32 + ln) * 2 + breg] = __halves2half2(hh0, hh1);
        }
    };

    float acc[2][2][4];
#pragma unroll
    for (int mf = 0; mf < 2; mf++)
#pragma unroll
        for (int nf = 0; nf < 2; nf++)
#pragma unroll
            for (int q = 0; q < 4; q++) acc[mf][nf][q] = 0.f;

    ldgA(0); ldgB(0);
    sts(0);

    for (int c = 0; c < IN_F / 32; c++) {
        __syncthreads();
        const int buf = c & 1;
        if (c + 1 < IN_F / 32) { ldgA((c + 1) * 32); ldgB((c + 1) * 32); }
        // adj loads for this iteration (results consumed after the MMA block)
        const long w0 = wbase + c * 4;
        int a0 = adj[w0 * 32 + lane];
        int a1 = adj[w0 * 32 + 32 + lane];
        int a2 = adj[w0 * 32 + 64 + lane];
        int a3 = adj[w0 * 32 + 96 + lane];
#pragma unroll
        for (int ks = 0; ks < 2; ks++) {
            uint4 ahi[2];
            uint2 bhi[2];
#pragma unroll
            for (int mf = 0; mf < 2; mf++)
                ahi[mf] = *(uint4*)&Ah[buf][((ks * 4 + wm * 2 + mf) * 32 + lane) * 4];
#pragma unroll
            for (int nf = 0; nf < 2; nf++)
                bhi[nf] = *(uint2*)&Bh[buf][((ks * 8 + wn * 2 + nf) * 32 + lane) * 2];
#pragma unroll
            for (int mf = 0; mf < 2; mf++) {
                uint32_t ah[4] = {ahi[mf].x, ahi[mf].y, ahi[mf].z, ahi[mf].w};
#pragma unroll
                for (int nf = 0; nf < 2; nf++) mma16816(acc[mf][nf], ah, bhi[nf]);
            }
        }
        if (c + 1 < IN_F / 32) sts((c + 1) & 1);
        // adjbits: ballot + store (4 words)
        {
            uint32_t m0 = __ballot_sync(0xFFFFFFFFu, a0 != 0);
            uint32_t m1 = __ballot_sync(0xFFFFFFFFu, a1 != 0);
            uint32_t m2 = __ballot_sync(0xFFFFFFFFu, a2 != 0);
            uint32_t m3 = __ballot_sync(0xFFFFFFFFu, a3 != 0);
            uint32_t mo = m0;
            mo = (lane == 1) ? m1 : mo;
            mo = (lane == 2) ? m2 : mo;
            mo = (lane == 3) ? m3 : mo;
            if (lane < 4) g_adjbits[w0 + lane] = mo;
        }
    }

    // ---- epilogue: stage tile, then score + bfrag ----
    const int rq = lane >> 2, cq = (lane & 3) * 2;
    __syncthreads();
#pragma unroll
    for (int mf = 0; mf < 2; mf++) {
        int r0 = (wm * 2 + mf) * 16 + rq;
#pragma unroll
        for (int nf = 0; nf < 2; nf++) {
            int col = (wn * 2 + nf) * 8 + cq;
            tile[r0][col]     = acc[mf][nf][0];
            tile[r0][col + 1] = acc[mf][nf][1];
            tile[r0 + 8][col]     = acc[mf][nf][2];
            tile[r0 + 8][col + 1] = acc[mf][nf][3];
        }
    }
    __syncthreads();

    if (tid < 128) {   // score: 64 rows x 2 heads
        int row = tid & 63, hh = tid >> 6;
        int node = bm + row;
        int head = (bn >> 5) + hh;
        const float* tp = &tile[row][hh * 32];
        float sl = 0.f, sr = 0.f;
#pragma unroll
        for (int c = 0; c < 8; c++) {
            float4 v = *(const float4*)&tp[c * 4];
            sl = fmaf(v.x, as[c*4+0], sl); sl = fmaf(v.y, as[c*4+1], sl);
            sl = fmaf(v.z, as[c*4+2], sl); sl = fmaf(v.w, as[c*4+3], sl);
            sr = fmaf(v.x, as[NF+c*4+0], sr); sr = fmaf(v.y, as[NF+c*4+1], sr);
            sr = fmaf(v.z, as[NF+c*4+2], sr); sr = fmaf(v.w, as[NF+c*4+3], sr);
        }
        const int o = head * N_NODES + node;
        g_u1h[o]  = __float2half_rn(expf(sr));
        g_u2h[o]  = __float2half_rn(expf(0.2f * sr));
        g_e1h[o]  = __float2half_rn(expf(sl));
        g_e2h[o]  = __float2half_rn(expf(0.2f * sl));
        g_thrh[o] = __float2half_rn(expf(-sl));
    }

    // bfrag: 40 fragments per CTA, 8 warps x 5
    const int n = lane >> 2, kq = (lane & 3) * 2;
#pragma unroll
    for (int t = 0; t < 5; t++) {
        int fid = wid * 5 + t;
        uint2 frag;
        int hh, jgl, nfr;
        if (fid < 32) {
            hh = fid >> 4; jgl = (fid >> 2) & 3; nfr = fid & 3;
            int f = nfr * 8 + n;
            float v[4];
#pragma unroll
            for (int r = 0; r < 2; r++)
#pragma unroll
                for (int s = 0; s < 2; s++)
                    v[r * 2 + s] = tile[jgl * 16 + r * 8 + kq + s][hh * 32 + f];
            frag = make_uint2(
                h2u(__halves2half2(__float2half_rn(v[0]), __float2half_rn(v[1]))),
                h2u(__halves2half2(__float2half_rn(v[2]), __float2half_rn(v[3]))));
        } else {
            int p = fid - 32;
            hh = p >> 2; jgl = p & 3; nfr = 4;
            uint32_t ones = (n == 0) ? 0x3C003C00u : 0u;
            frag = make_uint2(ones, ones);
        }
        int head = (bn >> 5) + hh;
        int jg = (bm >> 4) + jgl;
        g_bfragHI[((long)(head * 128 + jg) * 5 + nfr) * 32 + lane] = frag;
    }
}

// ---------------- K2: HMMA attention aggregation (128-row tiles, half2 W-gen) ----------------
__global__ __launch_bounds__(256, 1) void attn_kernel() {
    __shared__ uint32_t adjw[2][128];
    __shared__ __half u1s[2][128];   // [4 h][32 j]
    __shared__ __half u2s[2][128];

    const int tid = threadIdx.x, wid = tid >> 5, lane = tid & 31;
    const int i0 = blockIdx.x * 128;
    const int hg = blockIdx.y;
    const int sp = blockIdx.z;
    const int j00 = sp * JSPAN;

    const int hloc  = wid >> 1;
    const int hglob = hg * 4 + hloc;
    const int ihalf = (wid & 1) * 64;
    const int rq = lane >> 2;
    const int kq = (lane & 3) * 2;

    __half2 th2[4][2], e2b[4][2], ed[4][2];
#pragma unroll
    for (int mf = 0; mf < 4; mf++)
#pragma unroll
        for (int rs = 0; rs < 2; rs++) {
            int r = i0 + ihalf + mf * 16 + rq + rs * 8;
            __half e1 = g_e1h[hglob * N_NODES + r];
            __half e2 = g_e2h[hglob * N_NODES + r];
            th2[mf][rs] = __half2half2(g_thrh[hglob * N_NODES + r]);
            e2b[mf][rs] = __half2half2(e2);
            ed[mf][rs]  = __half2half2(__hsub(e1, e2));
        }

    float acc[4][5][4];
#pragma unroll
    for (int mf = 0; mf < 4; mf++)
#pragma unroll
        for (int nf = 0; nf < 5; nf++)
#pragma unroll
            for (int q = 0; q < 4; q++) acc[mf][nf][q] = 0.f;

    {   // stage chunk 0
        const int j0c = j00;
        if (tid < 128) {
            adjw[0][tid] = g_adjbits[(i0 + tid) * (N_NODES / 32) + (j0c >> 5)];
            u1s[0][tid] = g_u1h[(hg * 4 + (tid >> 5)) * N_NODES + j0c + (tid & 31)];
        } else {
            int q = tid - 128;
            u2s[0][q] = g_u2h[(hg * 4 + (q >> 5)) * N_NODES + j0c + (q & 31)];
        }
    }
    __syncthreads();

    for (int c = 0; c < 16; c++) {
        const int j0c = j00 + c * 32;
        const int buf = c & 1;
        uint2 bh[2][5];
#pragma unroll
        for (int ks = 0; ks < 2; ks++) {
            const long bbase = ((long)(hglob * 128 + (j0c >> 4) + ks) * 5) * 32 + lane;
#pragma unroll
            for (int nf = 0; nf < 5; nf++) bh[ks][nf] = g_bfragHI[bbase + nf * 32];
        }
        if (c + 1 < 16) {
            const int j0n = j0c + 32;
            if (tid < 128) {
                adjw[buf ^ 1][tid] = g_adjbits[(i0 + tid) * (N_NODES / 32) + (j0n >> 5)];
                u1s[buf ^ 1][tid] = g_u1h[(hg * 4 + (tid >> 5)) * N_NODES + j0n + (tid & 31)];
            } else {
                int q = tid - 128;
                u2s[buf ^ 1][q] = g_u2h[(hg * 4 + (q >> 5)) * N_NODES + j0n + (q & 31)];
            }
        }

#pragma unroll
        for (int kstep = 0; kstep < 2; kstep++) {
            const int jb = kstep * 16 + kq;
            __half2 u1a = *(const __half2*)&u1s[buf][hloc * 32 + jb];
            __half2 u1b = *(const __half2*)&u1s[buf][hloc * 32 + jb + 8];
            __half2 u2a = *(const __half2*)&u2s[buf][hloc * 32 + jb];
            __half2 u2b = *(const __half2*)&u2s[buf][hloc * 32 + jb + 8];
            __half2 uda = __hsub2(u1a, u2a);
            __half2 udb = __hsub2(u1b, u2b);

#pragma unroll
            for (int mf = 0; mf < 4; mf++) {
                uint32_t aw0 = adjw[buf][ihalf + mf * 16 + rq];
                uint32_t aw1 = adjw[buf][ihalf + mf * 16 + rq + 8];
                uint32_t areg[4];
#pragma unroll
                for (int rs = 0; rs < 2; rs++) {
                    uint32_t aw = rs ? aw1 : aw0;
                    __half2 th = th2[mf][rs], e2r = e2b[mf][rs], edr = ed[mf][rs];
                    uint32_t ba = (aw >> jb) & 3u;
                    uint32_t ma = ((ba & 1u) * 0x3C00u) | ((ba >> 1) * 0x3C000000u);
                    __half2 m  = __hge2(u1a, th);
                    __half2 t  = __hfma2(m, uda, u2a);
                    __half2 e  = __hfma2(m, edr, e2r);
                    __half2 w  = __hmul2(__hmul2(t, e), u2h2(ma));
                    areg[rs] = h2u(w);
                    uint32_t bb = (aw >> (jb + 8)) & 3u;
                    uint32_t mb = ((bb & 1u) * 0x3C00u) | ((bb >> 1) * 0x3C000000u);
                    __half2 m2 = __hge2(u1b, th);
                    __half2 t2 = __hfma2(m2, udb, u2b);
                    __half2 e2x = __hfma2(m2, edr, e2r);
                    __half2 w2 = __hmul2(__hmul2(t2, e2x), u2h2(mb));
                    areg[rs + 2] = h2u(w2);
                }
#pragma unroll
                for (int nf = 0; nf < 5; nf++) mma16816(acc[mf][nf], areg, bh[kstep][nf]);
            }
        }
        __syncthreads();
    }

#pragma unroll
    for (int mf = 0; mf < 4; mf++) {
        int r0 = i0 + ihalf + mf * 16 + rq;
        int r1 = r0 + 8;
#pragma unroll
        for (int nf = 0; nf < 4; nf++) {
            int f = nf * 8 + kq;
            *(float2*)&g_pnum[sp][r0 * GDIM + hglob * NF + f] =
                make_float2(acc[mf][nf][0], acc[mf][nf][1]);
            *(float2*)&g_pnum[sp][r1 * GDIM + hglob * NF + f] =
                make_float2(acc[mf][nf][2], acc[mf][nf][3]);
        }
        if ((lane & 3) == 0) {
            g_pz[sp][r0 * NH + hglob] = acc[mf][4][0];
            g_pz[sp][r1 * NH + hglob] = acc[mf][4][2];
        }
    }
}

// ---------------- K3: combine + normalize (4 floats/thread, 512 CTAs, MLP=8) ----------------
__global__ __launch_bounds__(256) void norm_kernel(float* __restrict__ out) {
    const int a4 = (blockIdx.x * 256 + threadIdx.x) * 4;
    const int ih = a4 >> 5;
    float4 v0 = *(const float4*)&g_pnum[0][a4];
    float4 v1 = *(const float4*)&g_pnum[1][a4];
    float4 v2 = *(const float4*)&g_pnum[2][a4];
    float4 v3 = *(const float4*)&g_pnum[3][a4];
    float z = (g_pz[0][ih] + g_pz[1][ih]) + (g_pz[2][ih] + g_pz[3][ih]);
    float inv = 1.0f / z;
    float4 r;
    r.x = ((v0.x + v1.x) + (v2.x + v3.x)) * inv;
    r.y = ((v0.y + v1.y) + (v2.y + v3.y)) * inv;
    r.z = ((v0.z + v1.z) + (v2.z + v3.z)) * inv;
    r.w = ((v0.w + v1.w) + (v2.w + v3.w)) * inv;
    *(float4*)&out[a4] = r;
}

extern "C" void kernel_launch(void* const* d_in, const int* in_sizes, int n_in,
                              void* d_out, int out_size) {
    const float* h_ptr = nullptr;
    const int*   adj   = nullptr;
    const float* W_ptr = nullptr;
    const float* a_ptr = nullptr;
    for (int i = 0; i < n_in; i++) {
        long sz = in_sizes[i];
        if (sz == (long)N_NODES * IN_F)          h_ptr = (const float*)d_in[i];
        else if (sz == (long)N_NODES * N_NODES)  adj   = (const int*)d_in[i];
        else if (sz == (long)IN_F * GDIM)        W_ptr = (const float*)d_in[i];
        else if (sz == 2 * NF)                   a_ptr = (const float*)d_in[i];
    }
    float* out = (float*)d_out;

    hgemm_fused<<<dim3(GDIM / 64, N_NODES / 64), 256>>>(h_ptr, W_ptr, a_ptr, adj);
    attn_kernel<<<dim3(N_NODES / 128, 2, NSPLIT), 256>>>();
    norm_kernel<<<(N_NODES * GDIM) / 1024, 256>>>(out);
}